// round 14
// baseline (speedup 1.0000x reference)
#include <cuda_runtime.h>
#include <cuda_bf16.h>
#include <cstdint>

#define NND 50000
#define NE  800000
#define HID 128

#define SCB 256
#define NSB ((NND + SCB - 1) / SCB)

#define PADB 272           // bytes per smem tile row (128 bf16 + 8 pad)
#define TILEB (128 * PADB)

#define SM_AHI 0
#define SM_ALO (SM_AHI + TILEB)
#define SM_WHI (SM_ALO + TILEB)
#define SM_WLO (SM_WHI + TILEB)
#define SM_FC  (SM_WLO + TILEB)
#define SM_TOTAL (SM_FC + 128 * 4 * 2 * 4)

// ---------------- device scratch ----------------
__device__ int   g_deg[NND];
__device__ int   g_rowptr[NND + 1];
__device__ int   g_cursor[NND];
__device__ int   g_col[NE];
__device__ int   g_part[NSB];
__device__ float g_bufA[(size_t)NND * HID];
__device__ float g_bufB[(size_t)NND * HID];
__device__ __nv_bfloat16 g_wb[8][16384];  // {W1a,W1b,W2a,W2b} x {hi,lo}, [n][k]
__device__ int   g_is64;

// ---------------- PTX helpers ----------------
__device__ __forceinline__ uint32_t smem_u32(const void* p) {
    uint32_t a;
    asm("{ .reg .u64 t; cvta.to.shared.u64 t, %1; cvt.u32.u64 %0, t; }" : "=r"(a) : "l"(p));
    return a;
}
__device__ __forceinline__ void ldsm_x4(uint32_t* r, uint32_t addr) {
    asm volatile("ldmatrix.sync.aligned.m8n8.x4.shared.b16 {%0,%1,%2,%3}, [%4];"
                 : "=r"(r[0]), "=r"(r[1]), "=r"(r[2]), "=r"(r[3]) : "r"(addr));
}
__device__ __forceinline__ void ldsm_x2(uint32_t* r, uint32_t addr) {
    asm volatile("ldmatrix.sync.aligned.m8n8.x2.shared.b16 {%0,%1}, [%2];"
                 : "=r"(r[0]), "=r"(r[1]) : "r"(addr));
}
__device__ __forceinline__ void mma16816(float* c, const uint32_t* a, const uint32_t* b) {
    asm volatile("mma.sync.aligned.m16n8k16.row.col.f32.bf16.bf16.f32 "
                 "{%0,%1,%2,%3}, {%4,%5,%6,%7}, {%8,%9}, {%0,%1,%2,%3};"
                 : "+f"(c[0]), "+f"(c[1]), "+f"(c[2]), "+f"(c[3])
                 : "r"(a[0]), "r"(a[1]), "r"(a[2]), "r"(a[3]), "r"(b[0]), "r"(b[1]));
}
__device__ __forceinline__ uint32_t pack_bf16_hi(float v0, float v1, uint32_t& lop) {
    __nv_bfloat16 h0 = __float2bfloat16(v0);
    __nv_bfloat16 h1 = __float2bfloat16(v1);
    __nv_bfloat16 l0 = __float2bfloat16(v0 - __bfloat162float(h0));
    __nv_bfloat16 l1 = __float2bfloat16(v1 - __bfloat162float(h1));
    lop = ((uint32_t)__bfloat16_as_ushort(l1) << 16) | __bfloat16_as_ushort(l0);
    return ((uint32_t)__bfloat16_as_ushort(h1) << 16) | __bfloat16_as_ushort(h0);
}

// ---------------- zero degrees + edge dtype detection (merged) ----------------
__global__ void k_zero_deg(const long long* __restrict__ ei) {
    int i = blockIdx.x * blockDim.x + threadIdx.x;
    if (i < NND) g_deg[i] = 0;
    if (blockIdx.x == 0 && threadIdx.x < 32) {
        int lane = threadIdx.x;
        unsigned long long h = ((unsigned long long)ei[lane]) >> 32;
        h |= ((unsigned long long)ei[lane + 32]) >> 32;
        unsigned any = __ballot_sync(0xffffffffu, h != 0ull);
        if (lane == 0) g_is64 = (any == 0u) ? 1 : 0;
    }
}

// ---------------- histogram + weight prep (merged; prep = 4 trailing blocks) ----------------
#define HISTB (NE / 256)   // 3125
__global__ void k_hist(const void* __restrict__ ei,
                       const float* __restrict__ W0, const float* __restrict__ W1,
                       const float* __restrict__ W2, const float* __restrict__ W3) {
    if (blockIdx.x >= HISTB) {
        int mat = blockIdx.x - HISTB;
        const float* W = (mat == 0) ? W0 : (mat == 1) ? W1 : (mat == 2) ? W2 : W3;
        uint32_t* hiB = reinterpret_cast<uint32_t*>(g_wb[mat * 2]);
        uint32_t* loB = reinterpret_cast<uint32_t*>(g_wb[mat * 2 + 1]);
        for (int idx = threadIdx.x; idx < 8192; idx += blockDim.x) {
            int kp = idx & 63, n = idx >> 6, k = kp * 2;
            float a0 = W[k * 128 + n];
            float a1 = W[(k + 1) * 128 + n];
            uint32_t lp, hp = pack_bf16_hi(a0, a1, lp);
            hiB[n * 64 + kp] = hp;
            loB[n * 64 + kp] = lp;
        }
        return;
    }
    int e = blockIdx.x * blockDim.x + threadIdx.x;
    int d;
    if (g_is64) d = (int)reinterpret_cast<const long long*>(ei)[NE + e];
    else        d = reinterpret_cast<const int*>(ei)[NE + e];
    atomicAdd(&g_deg[d], 1);
}

// ---------------- scan phase 1: per-block sums ----------------
__global__ void k_s1() {
    int b = blockIdx.x, t = threadIdx.x;
    int idx = b * SCB + t;
    int v = (idx < NND) ? g_deg[idx] : 0;
#pragma unroll
    for (int o = 16; o; o >>= 1) v += __shfl_down_sync(0xffffffffu, v, o);
    __shared__ int ws[8];
    if ((t & 31) == 0) ws[t >> 5] = v;
    __syncthreads();
    if (t == 0) {
        int s = 0;
#pragma unroll
        for (int i = 0; i < 8; i++) s += ws[i];
        g_part[b] = s;
    }
}

// ---------------- scan phase 2+3 fused: base = sum(part[0..b)), local scan, write ----------------
__global__ void k_s23() {
    int b = blockIdx.x, t = threadIdx.x, lane = t & 31, w = t >> 5;
    __shared__ int ws[8], wso[8];
    __shared__ int sbase;
    // reduce partials before this block (b <= 195 < 256)
    int pv = (t < b) ? g_part[t] : 0;
#pragma unroll
    for (int o = 16; o; o >>= 1) pv += __shfl_down_sync(0xffffffffu, pv, o);
    if (lane == 0) ws[w] = pv;
    __syncthreads();
    if (t == 0) {
        int s = 0;
#pragma unroll
        for (int i = 0; i < 8; i++) s += ws[i];
        sbase = s;
        if (b == 0) g_rowptr[NND] = NE;
    }
    __syncthreads();
    const int base = sbase;
    // local exclusive scan over this block's 256 degrees
    int idx = b * SCB + t;
    int v = (idx < NND) ? g_deg[idx] : 0;
    int iv = v;
#pragma unroll
    for (int o = 1; o < 32; o <<= 1) {
        int u = __shfl_up_sync(0xffffffffu, iv, o);
        if (lane >= o) iv += u;
    }
    __syncthreads();
    if (lane == 31) ws[w] = iv;
    __syncthreads();
    if (t == 0) {
        int run = 0;
#pragma unroll
        for (int i = 0; i < 8; i++) { wso[i] = run; run += ws[i]; }
    }
    __syncthreads();
    int excl = base + wso[w] + iv - v;
    if (idx < NND) { g_rowptr[idx] = excl; g_cursor[idx] = excl; }
}

__global__ void k_fill(const void* __restrict__ ei) {
    int e = blockIdx.x * blockDim.x + threadIdx.x;
    if (e >= NE) return;
    int s, d;
    if (g_is64) {
        s = (int)reinterpret_cast<const long long*>(ei)[e];
        d = (int)reinterpret_cast<const long long*>(ei)[NE + e];
    } else {
        s = reinterpret_cast<const int*>(ei)[e];
        d = reinterpret_cast<const int*>(ei)[NE + e];
    }
    int pos = atomicAdd(&g_cursor[d], 1);
    g_col[pos] = s;
}

// ---------------- static gather (warp per node, ILP x4) ----------------
__global__ void k_gather(const float4* __restrict__ in4, float4* __restrict__ out4) {
    int node = (int)((blockIdx.x * blockDim.x + threadIdx.x) >> 5);
    if (node >= NND) return;
    int lane = threadIdx.x & 31;
    float4 a0 = in4[(size_t)node * 32 + lane];
    float4 a1 = make_float4(0.f, 0.f, 0.f, 0.f);
    int beg = g_rowptr[node], end = g_rowptr[node + 1];
    int k = beg;
    for (; k + 4 <= end; k += 4) {
        int j0 = g_col[k], j1 = g_col[k + 1], j2 = g_col[k + 2], j3 = g_col[k + 3];
        float4 v0 = in4[(size_t)j0 * 32 + lane];
        float4 v1 = in4[(size_t)j1 * 32 + lane];
        float4 v2 = in4[(size_t)j2 * 32 + lane];
        float4 v3 = in4[(size_t)j3 * 32 + lane];
        a0.x += v0.x; a0.y += v0.y; a0.z += v0.z; a0.w += v0.w;
        a1.x += v1.x; a1.y += v1.y; a1.z += v1.z; a1.w += v1.w;
        a0.x += v2.x; a0.y += v2.y; a0.z += v2.z; a0.w += v2.w;
        a1.x += v3.x; a1.y += v3.y; a1.z += v3.z; a1.w += v3.w;
    }
    for (; k < end; k++) {
        int j = g_col[k];
        float4 v = in4[(size_t)j * 32 + lane];
        a0.x += v.x; a0.y += v.y; a0.z += v.z; a0.w += v.w;
    }
    a0.x += a1.x; a0.y += a1.y; a0.z += a1.z; a0.w += a1.w;
    out4[(size_t)node * 32 + lane] = a0;
}

// ---------------- GEMM core: 3-phase bf16 split, acc fp32 (16-warp layout) ----------------
// warp (wm 0..3, wn 0..3): rows wm*32..+32, cols wn*32..+32
__device__ __forceinline__ void do_gemm(uint32_t smb, int wm, int wn, int lane,
                                        float acc[2][4][4]) {
#pragma unroll
    for (int mt = 0; mt < 2; mt++)
#pragma unroll
        for (int nt = 0; nt < 4; nt++)
#pragma unroll
            for (int i = 0; i < 4; i++) acc[mt][nt][i] = 0.f;

    const uint32_t a_bases[3] = { smb + SM_AHI, smb + SM_AHI, smb + SM_ALO };
    const uint32_t w_bases[3] = { smb + SM_WHI, smb + SM_WLO, smb + SM_WHI };

    const int a_row0 = wm * 32 + (lane & 15);
    const int a_cofs = (lane >> 4) * 8;
    const int b_row0 = wn * 32 + (lane & 7);
    const int b_cofs = ((lane >> 3) & 1) * 8;

#pragma unroll
    for (int p = 0; p < 3; p++) {
        const uint32_t Ab = a_bases[p];
        const uint32_t Wb = w_bases[p];
#pragma unroll
        for (int ks = 0; ks < 8; ks++) {
            const int k0 = ks * 16;
            uint32_t afrag[2][4];
#pragma unroll
            for (int mt = 0; mt < 2; mt++)
                ldsm_x4(afrag[mt], Ab + (uint32_t)(a_row0 + mt * 16) * PADB
                                      + (uint32_t)(k0 + a_cofs) * 2);
            uint32_t bfrag[4][2];
#pragma unroll
            for (int nt = 0; nt < 4; nt++)
                ldsm_x2(bfrag[nt], Wb + (uint32_t)(b_row0 + nt * 8) * PADB
                                      + (uint32_t)(k0 + b_cofs) * 2);
#pragma unroll
            for (int mt = 0; mt < 2; mt++)
#pragma unroll
                for (int nt = 0; nt < 4; nt++)
                    mma16816(acc[mt][nt], afrag[mt], bfrag[nt]);
        }
    }
}

// ---------------- MLP kernel: 2 GEMMs + epilogues (512 threads) ----------------
__global__ void __launch_bounds__(512, 1) k_mlp_mma(
    const float* __restrict__ A,
    const __nv_bfloat16* __restrict__ WaHi, const __nv_bfloat16* __restrict__ WaLo,
    const __nv_bfloat16* __restrict__ WbHi, const __nv_bfloat16* __restrict__ WbLo,
    const float* __restrict__ ba, const float* __restrict__ bb,
    float* __restrict__ out, int final_relu,
    const float* __restrict__ Wfc, const float* __restrict__ bfc) {
    extern __shared__ char sm[];
    const uint32_t smb = smem_u32(sm);
    const int tid = threadIdx.x;
    const int wid = tid >> 5;
    const int lane = tid & 31;
    const int wm = wid & 3;
    const int wn = wid >> 2;      // 0..3
    const int m_base = blockIdx.x * 128;

    // ---- load A tile: fp32 -> bf16 hi/lo (warp per 8 rows) ----
    {
#pragma unroll
        for (int it = 0; it < 8; it++) {
            int r = wid * 8 + it;
            int m = m_base + r;
            float4 v = make_float4(0.f, 0.f, 0.f, 0.f);
            if (m < NND) v = *reinterpret_cast<const float4*>(A + (size_t)m * 128 + lane * 4);
            uint32_t l0, l1;
            uint32_t h0 = pack_bf16_hi(v.x, v.y, l0);
            uint32_t h1 = pack_bf16_hi(v.z, v.w, l1);
            uint32_t off = (uint32_t)r * PADB + (uint32_t)lane * 8;
            *reinterpret_cast<uint2*>(sm + SM_AHI + off) = make_uint2(h0, h1);
            *reinterpret_cast<uint2*>(sm + SM_ALO + off) = make_uint2(l0, l1);
        }
    }
    // ---- copy Wa blobs ----
    {
        const float4* sh = reinterpret_cast<const float4*>(WaHi);
        const float4* sl = reinterpret_cast<const float4*>(WaLo);
#pragma unroll
        for (int i = 0; i < 4; i++) {
            int idx = i * 512 + tid;          // float4 index, 2048 total
            int row = idx >> 4, c16 = idx & 15;
            uint32_t off = (uint32_t)row * PADB + (uint32_t)c16 * 16;
            *reinterpret_cast<float4*>(sm + SM_WHI + off) = sh[idx];
            *reinterpret_cast<float4*>(sm + SM_WLO + off) = sl[idx];
        }
    }
    __syncthreads();

    float acc[2][4][4];
    do_gemm(smb, wm, wn, lane, acc);
    __syncthreads();

    // ---- epilogue 1: bias + relu -> back into A tile ----
    {
        const int r0 = wm * 32 + (lane >> 2);
#pragma unroll
        for (int mt = 0; mt < 2; mt++) {
#pragma unroll
            for (int nt = 0; nt < 4; nt++) {
                int c = wn * 32 + nt * 8 + (lane & 3) * 2;
                float bc0 = __ldg(ba + c), bc1 = __ldg(ba + c + 1);
                float v0 = acc[mt][nt][0] + bc0;
                float v1 = acc[mt][nt][1] + bc1;
                float v2 = acc[mt][nt][2] + bc0;
                float v3 = acc[mt][nt][3] + bc1;
                v0 = v0 > 0.f ? v0 : 0.f; v1 = v1 > 0.f ? v1 : 0.f;
                v2 = v2 > 0.f ? v2 : 0.f; v3 = v3 > 0.f ? v3 : 0.f;
                int r = r0 + mt * 16;
                uint32_t lo;
                uint32_t hi = pack_bf16_hi(v0, v1, lo);
                uint32_t off = (uint32_t)r * PADB + (uint32_t)c * 2;
                *reinterpret_cast<uint32_t*>(sm + SM_AHI + off) = hi;
                *reinterpret_cast<uint32_t*>(sm + SM_ALO + off) = lo;
                hi = pack_bf16_hi(v2, v3, lo);
                off = (uint32_t)(r + 8) * PADB + (uint32_t)c * 2;
                *reinterpret_cast<uint32_t*>(sm + SM_AHI + off) = hi;
                *reinterpret_cast<uint32_t*>(sm + SM_ALO + off) = lo;
            }
        }
    }
    // ---- copy Wb blobs ----
    {
        const float4* sh = reinterpret_cast<const float4*>(WbHi);
        const float4* sl = reinterpret_cast<const float4*>(WbLo);
#pragma unroll
        for (int i = 0; i < 4; i++) {
            int idx = i * 512 + tid;
            int row = idx >> 4, c16 = idx & 15;
            uint32_t off = (uint32_t)row * PADB + (uint32_t)c16 * 16;
            *reinterpret_cast<float4*>(sm + SM_WHI + off) = sh[idx];
            *reinterpret_cast<float4*>(sm + SM_WLO + off) = sl[idx];
        }
    }
    __syncthreads();

    do_gemm(smb, wm, wn, lane, acc);

    // ---- epilogue 2 ----
    const int r0 = wm * 32 + (lane >> 2);
    if (Wfc == nullptr) {
#pragma unroll
        for (int mt = 0; mt < 2; mt++) {
            int ra = m_base + r0 + mt * 16;
            int rb = ra + 8;
#pragma unroll
            for (int nt = 0; nt < 4; nt++) {
                int c = wn * 32 + nt * 8 + (lane & 3) * 2;
                float bc0 = __ldg(bb + c), bc1 = __ldg(bb + c + 1);
                float v0 = acc[mt][nt][0] + bc0;
                float v1 = acc[mt][nt][1] + bc1;
                float v2 = acc[mt][nt][2] + bc0;
                float v3 = acc[mt][nt][3] + bc1;
                if (final_relu) {
                    v0 = v0 > 0.f ? v0 : 0.f; v1 = v1 > 0.f ? v1 : 0.f;
                    v2 = v2 > 0.f ? v2 : 0.f; v3 = v3 > 0.f ? v3 : 0.f;
                }
                if (ra < NND) *reinterpret_cast<float2*>(out + (size_t)ra * 128 + c) = make_float2(v0, v1);
                if (rb < NND) *reinterpret_cast<float2*>(out + (size_t)rb * 128 + c) = make_float2(v2, v3);
            }
        }
    } else {
        float* fcb = reinterpret_cast<float*>(sm + SM_FC);  // [128 rows][4 wn][2]
#pragma unroll
        for (int mt = 0; mt < 2; mt++) {
            float sa0 = 0.f, sa1 = 0.f, sb0 = 0.f, sb1 = 0.f;
#pragma unroll
            for (int nt = 0; nt < 4; nt++) {
                int c = wn * 32 + nt * 8 + (lane & 3) * 2;
                float bc0 = __ldg(bb + c), bc1 = __ldg(bb + c + 1);
                float w00 = __ldg(Wfc + c * 2),       w01 = __ldg(Wfc + c * 2 + 1);
                float w10 = __ldg(Wfc + (c + 1) * 2), w11 = __ldg(Wfc + (c + 1) * 2 + 1);
                float v0 = acc[mt][nt][0] + bc0;
                float v1 = acc[mt][nt][1] + bc1;
                float v2 = acc[mt][nt][2] + bc0;
                float v3 = acc[mt][nt][3] + bc1;
                sa0 += v0 * w00 + v1 * w10;
                sa1 += v0 * w01 + v1 * w11;
                sb0 += v2 * w00 + v3 * w10;
                sb1 += v2 * w01 + v3 * w11;
            }
#pragma unroll
            for (int o = 1; o < 4; o <<= 1) {
                sa0 += __shfl_xor_sync(0xffffffffu, sa0, o);
                sa1 += __shfl_xor_sync(0xffffffffu, sa1, o);
                sb0 += __shfl_xor_sync(0xffffffffu, sb0, o);
                sb1 += __shfl_xor_sync(0xffffffffu, sb1, o);
            }
            if ((lane & 3) == 0) {
                int r = r0 + mt * 16;
                fcb[(r * 4 + wn) * 2 + 0] = sa0;
                fcb[(r * 4 + wn) * 2 + 1] = sa1;
                fcb[((r + 8) * 4 + wn) * 2 + 0] = sb0;
                fcb[((r + 8) * 4 + wn) * 2 + 1] = sb1;
            }
        }
        __syncthreads();
        if (tid < 128) {
            int m = m_base + tid;
            if (m < NND) {
                float o0 = fcb[tid * 8 + 0] + fcb[tid * 8 + 2] + fcb[tid * 8 + 4] + fcb[tid * 8 + 6];
                float o1 = fcb[tid * 8 + 1] + fcb[tid * 8 + 3] + fcb[tid * 8 + 5] + fcb[tid * 8 + 7];
                out[(size_t)m * 2 + 0] = o0 + __ldg(bfc + 0);
                out[(size_t)m * 2 + 1] = o1 + __ldg(bfc + 1);
            }
        }
    }
}

// ---------------- launch ----------------
extern "C" void kernel_launch(void* const* d_in, const int* in_sizes, int n_in,
                              void* d_out, int out_size) {
    const float* x   = (const float*)d_in[0];
    const void*  ei  = d_in[1];
    const float* W1a = (const float*)d_in[2];
    const float* b1a = (const float*)d_in[3];
    const float* W1b = (const float*)d_in[4];
    const float* b1b = (const float*)d_in[5];
    const float* W2a = (const float*)d_in[6];
    const float* b2a = (const float*)d_in[7];
    const float* W2b = (const float*)d_in[8];
    const float* b2b = (const float*)d_in[9];
    const float* Wfc = (const float*)d_in[10];
    const float* bfc = (const float*)d_in[11];
    float* out = (float*)d_out;

    void *pA = nullptr, *pB = nullptr, *pW = nullptr;
    cudaGetSymbolAddress(&pA, g_bufA);
    cudaGetSymbolAddress(&pB, g_bufB);
    cudaGetSymbolAddress(&pW, g_wb);
    const __nv_bfloat16* wb = (const __nv_bfloat16*)pW;

    cudaFuncSetAttribute(k_mlp_mma, cudaFuncAttributeMaxDynamicSharedMemorySize, SM_TOTAL);

    const int GMLP = (NND + 127) / 128;   // 391
    const int GW   = (NND + 7) / 8;       // static warp-per-node gather

    k_zero_deg<<<(NND + 255) / 256, 256>>>((const long long*)ei);
    k_hist<<<HISTB + 4, 256>>>(ei, W1a, W1b, W2a, W2b);
    k_s1<<<NSB, SCB>>>();
    k_s23<<<NSB, SCB>>>();
    k_fill<<<NE / 256, 256>>>(ei);

    // layer 1
    k_gather<<<GW, 256>>>((const float4*)x, (float4*)pA);
    k_mlp_mma<<<GMLP, 512, SM_TOTAL>>>((const float*)pA,
        wb + 0 * 16384, wb + 1 * 16384, wb + 2 * 16384, wb + 3 * 16384,
        b1a, b1b, (float*)pB, 1, nullptr, nullptr);
    // layer 2 + FC head
    k_gather<<<GW, 256>>>((const float4*)pB, (float4*)pA);
    k_mlp_mma<<<GMLP, 512, SM_TOTAL>>>((const float*)pA,
        wb + 4 * 16384, wb + 5 * 16384, wb + 6 * 16384, wb + 7 * 16384,
        b2a, b2b, out, 0, Wfc, bfc);
}

// round 15
// speedup vs baseline: 1.0018x; 1.0018x over previous
#include <cuda_runtime.h>
#include <cuda_bf16.h>
#include <cstdint>

#define NND 50000
#define NE  800000
#define HID 128

#define SCB 256
#define NSB ((NND + SCB - 1) / SCB)

#define PADB 272           // bytes per smem tile row (128 bf16 + 8 pad)
#define TILEB (128 * PADB)

#define SM_AHI 0
#define SM_ALO (SM_AHI + TILEB)
#define SM_WHI (SM_ALO + TILEB)
#define SM_WLO (SM_WHI + TILEB)
#define SM_FC  (SM_WLO + TILEB)
#define SM_TOTAL (SM_FC + 128 * 4 * 4)

// ---------------- device scratch ----------------
__device__ int   g_deg[NND];
__device__ int   g_rowptr[NND + 1];
__device__ int   g_cursor[NND];
__device__ int   g_col[NE];
__device__ int   g_part[NSB];
__device__ float g_bufA[(size_t)NND * HID];
__device__ float g_bufB[(size_t)NND * HID];
__device__ __nv_bfloat16 g_wb[8][16384];  // {W1a,W1b,W2a,W2b} x {hi,lo}, [n][k]
__device__ int   g_is64;

// ---------------- PTX helpers ----------------
__device__ __forceinline__ uint32_t smem_u32(const void* p) {
    uint32_t a;
    asm("{ .reg .u64 t; cvta.to.shared.u64 t, %1; cvt.u32.u64 %0, t; }" : "=r"(a) : "l"(p));
    return a;
}
__device__ __forceinline__ void ldsm_x4(uint32_t* r, uint32_t addr) {
    asm volatile("ldmatrix.sync.aligned.m8n8.x4.shared.b16 {%0,%1,%2,%3}, [%4];"
                 : "=r"(r[0]), "=r"(r[1]), "=r"(r[2]), "=r"(r[3]) : "r"(addr));
}
__device__ __forceinline__ void ldsm_x2(uint32_t* r, uint32_t addr) {
    asm volatile("ldmatrix.sync.aligned.m8n8.x2.shared.b16 {%0,%1}, [%2];"
                 : "=r"(r[0]), "=r"(r[1]) : "r"(addr));
}
__device__ __forceinline__ void mma16816(float* c, const uint32_t* a, const uint32_t* b) {
    asm volatile("mma.sync.aligned.m16n8k16.row.col.f32.bf16.bf16.f32 "
                 "{%0,%1,%2,%3}, {%4,%5,%6,%7}, {%8,%9}, {%0,%1,%2,%3};"
                 : "+f"(c[0]), "+f"(c[1]), "+f"(c[2]), "+f"(c[3])
                 : "r"(a[0]), "r"(a[1]), "r"(a[2]), "r"(a[3]), "r"(b[0]), "r"(b[1]));
}
__device__ __forceinline__ uint32_t pack_bf16_hi(float v0, float v1, uint32_t& lop) {
    __nv_bfloat16 h0 = __float2bfloat16(v0);
    __nv_bfloat16 h1 = __float2bfloat16(v1);
    __nv_bfloat16 l0 = __float2bfloat16(v0 - __bfloat162float(h0));
    __nv_bfloat16 l1 = __float2bfloat16(v1 - __bfloat162float(h1));
    lop = ((uint32_t)__bfloat16_as_ushort(l1) << 16) | __bfloat16_as_ushort(l0);
    return ((uint32_t)__bfloat16_as_ushort(h1) << 16) | __bfloat16_as_ushort(h0);
}

// ---------------- zero degrees + edge dtype detection (merged) ----------------
__global__ void k_zero_deg(const long long* __restrict__ ei) {
    int i = blockIdx.x * blockDim.x + threadIdx.x;
    if (i < NND) g_deg[i] = 0;
    if (blockIdx.x == 0 && threadIdx.x < 32) {
        int lane = threadIdx.x;
        unsigned long long h = ((unsigned long long)ei[lane]) >> 32;
        h |= ((unsigned long long)ei[lane + 32]) >> 32;
        unsigned any = __ballot_sync(0xffffffffu, h != 0ull);
        if (lane == 0) g_is64 = (any == 0u) ? 1 : 0;
    }
}

// ---------------- histogram + weight prep (merged; prep = 4 trailing blocks) ----------------
#define HISTB (NE / 256)   // 3125
__global__ void k_hist(const void* __restrict__ ei,
                       const float* __restrict__ W0, const float* __restrict__ W1,
                       const float* __restrict__ W2, const float* __restrict__ W3) {
    if (blockIdx.x >= HISTB) {
        int mat = blockIdx.x - HISTB;
        const float* W = (mat == 0) ? W0 : (mat == 1) ? W1 : (mat == 2) ? W2 : W3;
        uint32_t* hiB = reinterpret_cast<uint32_t*>(g_wb[mat * 2]);
        uint32_t* loB = reinterpret_cast<uint32_t*>(g_wb[mat * 2 + 1]);
        for (int idx = threadIdx.x; idx < 8192; idx += blockDim.x) {
            int kp = idx & 63, n = idx >> 6, k = kp * 2;
            float a0 = W[k * 128 + n];
            float a1 = W[(k + 1) * 128 + n];
            uint32_t lp, hp = pack_bf16_hi(a0, a1, lp);
            hiB[n * 64 + kp] = hp;
            loB[n * 64 + kp] = lp;
        }
        return;
    }
    int e = blockIdx.x * blockDim.x + threadIdx.x;
    int d;
    if (g_is64) d = (int)reinterpret_cast<const long long*>(ei)[NE + e];
    else        d = reinterpret_cast<const int*>(ei)[NE + e];
    atomicAdd(&g_deg[d], 1);
}

// ---------------- scan phase 1: per-block sums ----------------
__global__ void k_s1() {
    int b = blockIdx.x, t = threadIdx.x;
    int idx = b * SCB + t;
    int v = (idx < NND) ? g_deg[idx] : 0;
#pragma unroll
    for (int o = 16; o; o >>= 1) v += __shfl_down_sync(0xffffffffu, v, o);
    __shared__ int ws[8];
    if ((t & 31) == 0) ws[t >> 5] = v;
    __syncthreads();
    if (t == 0) {
        int s = 0;
#pragma unroll
        for (int i = 0; i < 8; i++) s += ws[i];
        g_part[b] = s;
    }
}

// ---------------- scan phase 2+3 fused: base = sum(part[0..b)), local scan, write ----------------
__global__ void k_s23() {
    int b = blockIdx.x, t = threadIdx.x, lane = t & 31, w = t >> 5;
    __shared__ int ws[8], wso[8];
    __shared__ int sbase;
    int pv = (t < b) ? g_part[t] : 0;
#pragma unroll
    for (int o = 16; o; o >>= 1) pv += __shfl_down_sync(0xffffffffu, pv, o);
    if (lane == 0) ws[w] = pv;
    __syncthreads();
    if (t == 0) {
        int s = 0;
#pragma unroll
        for (int i = 0; i < 8; i++) s += ws[i];
        sbase = s;
        if (b == 0) g_rowptr[NND] = NE;
    }
    __syncthreads();
    const int base = sbase;
    int idx = b * SCB + t;
    int v = (idx < NND) ? g_deg[idx] : 0;
    int iv = v;
#pragma unroll
    for (int o = 1; o < 32; o <<= 1) {
        int u = __shfl_up_sync(0xffffffffu, iv, o);
        if (lane >= o) iv += u;
    }
    __syncthreads();
    if (lane == 31) ws[w] = iv;
    __syncthreads();
    if (t == 0) {
        int run = 0;
#pragma unroll
        for (int i = 0; i < 8; i++) { wso[i] = run; run += ws[i]; }
    }
    __syncthreads();
    int excl = base + wso[w] + iv - v;
    if (idx < NND) { g_rowptr[idx] = excl; g_cursor[idx] = excl; }
}

__global__ void k_fill(const void* __restrict__ ei) {
    int e = blockIdx.x * blockDim.x + threadIdx.x;
    if (e >= NE) return;
    int s, d;
    if (g_is64) {
        s = (int)reinterpret_cast<const long long*>(ei)[e];
        d = (int)reinterpret_cast<const long long*>(ei)[NE + e];
    } else {
        s = reinterpret_cast<const int*>(ei)[e];
        d = reinterpret_cast<const int*>(ei)[NE + e];
    }
    int pos = atomicAdd(&g_cursor[d], 1);
    g_col[pos] = s;
}

// ---------------- static gather (warp per node, ILP x8, 4 accumulators) ----------------
__global__ void k_gather(const float4* __restrict__ in4, float4* __restrict__ out4) {
    int node = (int)((blockIdx.x * blockDim.x + threadIdx.x) >> 5);
    if (node >= NND) return;
    int lane = threadIdx.x & 31;
    float4 a0 = in4[(size_t)node * 32 + lane];
    float4 a1 = make_float4(0.f, 0.f, 0.f, 0.f);
    float4 a2 = make_float4(0.f, 0.f, 0.f, 0.f);
    float4 a3 = make_float4(0.f, 0.f, 0.f, 0.f);
    int beg = g_rowptr[node], end = g_rowptr[node + 1];
    int k = beg;
    for (; k + 8 <= end; k += 8) {
        int j0 = g_col[k],     j1 = g_col[k + 1], j2 = g_col[k + 2], j3 = g_col[k + 3];
        int j4 = g_col[k + 4], j5 = g_col[k + 5], j6 = g_col[k + 6], j7 = g_col[k + 7];
        float4 v0 = in4[(size_t)j0 * 32 + lane];
        float4 v1 = in4[(size_t)j1 * 32 + lane];
        float4 v2 = in4[(size_t)j2 * 32 + lane];
        float4 v3 = in4[(size_t)j3 * 32 + lane];
        float4 v4 = in4[(size_t)j4 * 32 + lane];
        float4 v5 = in4[(size_t)j5 * 32 + lane];
        float4 v6 = in4[(size_t)j6 * 32 + lane];
        float4 v7 = in4[(size_t)j7 * 32 + lane];
        a0.x += v0.x; a0.y += v0.y; a0.z += v0.z; a0.w += v0.w;
        a1.x += v1.x; a1.y += v1.y; a1.z += v1.z; a1.w += v1.w;
        a2.x += v2.x; a2.y += v2.y; a2.z += v2.z; a2.w += v2.w;
        a3.x += v3.x; a3.y += v3.y; a3.z += v3.z; a3.w += v3.w;
        a0.x += v4.x; a0.y += v4.y; a0.z += v4.z; a0.w += v4.w;
        a1.x += v5.x; a1.y += v5.y; a1.z += v5.z; a1.w += v5.w;
        a2.x += v6.x; a2.y += v6.y; a2.z += v6.z; a2.w += v6.w;
        a3.x += v7.x; a3.y += v7.y; a3.z += v7.z; a3.w += v7.w;
    }
    for (; k + 4 <= end; k += 4) {
        int j0 = g_col[k], j1 = g_col[k + 1], j2 = g_col[k + 2], j3 = g_col[k + 3];
        float4 v0 = in4[(size_t)j0 * 32 + lane];
        float4 v1 = in4[(size_t)j1 * 32 + lane];
        float4 v2 = in4[(size_t)j2 * 32 + lane];
        float4 v3 = in4[(size_t)j3 * 32 + lane];
        a0.x += v0.x; a0.y += v0.y; a0.z += v0.z; a0.w += v0.w;
        a1.x += v1.x; a1.y += v1.y; a1.z += v1.z; a1.w += v1.w;
        a2.x += v2.x; a2.y += v2.y; a2.z += v2.z; a2.w += v2.w;
        a3.x += v3.x; a3.y += v3.y; a3.z += v3.z; a3.w += v3.w;
    }
    for (; k < end; k++) {
        int j = g_col[k];
        float4 v = in4[(size_t)j * 32 + lane];
        a0.x += v.x; a0.y += v.y; a0.z += v.z; a0.w += v.w;
    }
    a0.x += a1.x + a2.x + a3.x;
    a0.y += a1.y + a2.y + a3.y;
    a0.z += a1.z + a2.z + a3.z;
    a0.w += a1.w + a2.w + a3.w;
    out4[(size_t)node * 32 + lane] = a0;
}

// ---------------- GEMM core: 3-phase bf16 split, acc in fp32 (8-warp layout) ----------------
// warp (wm 0..3, wn 0..1): rows wm*32..+32, cols wn*64..+64
__device__ __forceinline__ void do_gemm(uint32_t smb, int wm, int wn, int lane,
                                        float acc[2][8][4]) {
#pragma unroll
    for (int mt = 0; mt < 2; mt++)
#pragma unroll
        for (int nt = 0; nt < 8; nt++)
#pragma unroll
            for (int i = 0; i < 4; i++) acc[mt][nt][i] = 0.f;

    const uint32_t a_bases[3] = { smb + SM_AHI, smb + SM_AHI, smb + SM_ALO };
    const uint32_t w_bases[3] = { smb + SM_WHI, smb + SM_WLO, smb + SM_WHI };

    const int a_row0 = wm * 32 + (lane & 15);
    const int a_cofs = (lane >> 4) * 8;
    const int b_row0 = wn * 64 + (lane & 7);
    const int b_cofs = ((lane >> 3) & 1) * 8;

#pragma unroll
    for (int p = 0; p < 3; p++) {
        const uint32_t Ab = a_bases[p];
        const uint32_t Wb = w_bases[p];
#pragma unroll
        for (int ks = 0; ks < 8; ks++) {
            const int k0 = ks * 16;
            uint32_t afrag[2][4];
#pragma unroll
            for (int mt = 0; mt < 2; mt++)
                ldsm_x4(afrag[mt], Ab + (uint32_t)(a_row0 + mt * 16) * PADB
                                      + (uint32_t)(k0 + a_cofs) * 2);
            uint32_t bfrag[8][2];
#pragma unroll
            for (int nt = 0; nt < 8; nt++)
                ldsm_x2(bfrag[nt], Wb + (uint32_t)(b_row0 + nt * 8) * PADB
                                      + (uint32_t)(k0 + b_cofs) * 2);
#pragma unroll
            for (int mt = 0; mt < 2; mt++)
#pragma unroll
                for (int nt = 0; nt < 8; nt++)
                    mma16816(acc[mt][nt], afrag[mt], bfrag[nt]);
        }
    }
}

// ---------------- MLP kernel: 2 GEMMs + epilogues (256 threads, proven) ----------------
__global__ void __launch_bounds__(256, 1) k_mlp_mma(
    const float* __restrict__ A,
    const __nv_bfloat16* __restrict__ WaHi, const __nv_bfloat16* __restrict__ WaLo,
    const __nv_bfloat16* __restrict__ WbHi, const __nv_bfloat16* __restrict__ WbLo,
    const float* __restrict__ ba, const float* __restrict__ bb,
    float* __restrict__ out, int final_relu,
    const float* __restrict__ Wfc, const float* __restrict__ bfc) {
    extern __shared__ char sm[];
    const uint32_t smb = smem_u32(sm);
    const int tid = threadIdx.x;
    const int wid = tid >> 5;
    const int lane = tid & 31;
    const int wm = wid & 3;
    const int wn = wid >> 2;
    const int m_base = blockIdx.x * 128;

    // ---- load A tile: fp32 -> bf16 hi/lo ----
    {
#pragma unroll
        for (int it = 0; it < 16; it++) {
            int r = wid * 16 + it;
            int m = m_base + r;
            float4 v = make_float4(0.f, 0.f, 0.f, 0.f);
            if (m < NND) v = *reinterpret_cast<const float4*>(A + (size_t)m * 128 + lane * 4);
            uint32_t l0, l1;
            uint32_t h0 = pack_bf16_hi(v.x, v.y, l0);
            uint32_t h1 = pack_bf16_hi(v.z, v.w, l1);
            uint32_t off = (uint32_t)r * PADB + (uint32_t)lane * 8;
            *reinterpret_cast<uint2*>(sm + SM_AHI + off) = make_uint2(h0, h1);
            *reinterpret_cast<uint2*>(sm + SM_ALO + off) = make_uint2(l0, l1);
        }
    }
    // ---- copy Wa blobs ----
    {
        const float4* sh = reinterpret_cast<const float4*>(WaHi);
        const float4* sl = reinterpret_cast<const float4*>(WaLo);
#pragma unroll
        for (int i = 0; i < 8; i++) {
            int idx = i * 256 + tid;
            int row = idx >> 4, c16 = idx & 15;
            uint32_t off = (uint32_t)row * PADB + (uint32_t)c16 * 16;
            *reinterpret_cast<float4*>(sm + SM_WHI + off) = sh[idx];
            *reinterpret_cast<float4*>(sm + SM_WLO + off) = sl[idx];
        }
    }
    __syncthreads();

    float acc[2][8][4];
    do_gemm(smb, wm, wn, lane, acc);
    __syncthreads();

    // ---- epilogue 1: bias + relu -> back into A tile ----
    {
        const int r0 = wm * 32 + (lane >> 2);
#pragma unroll
        for (int mt = 0; mt < 2; mt++) {
#pragma unroll
            for (int nt = 0; nt < 8; nt++) {
                int c = wn * 64 + nt * 8 + (lane & 3) * 2;
                float bc0 = __ldg(ba + c), bc1 = __ldg(ba + c + 1);
                float v0 = acc[mt][nt][0] + bc0;
                float v1 = acc[mt][nt][1] + bc1;
                float v2 = acc[mt][nt][2] + bc0;
                float v3 = acc[mt][nt][3] + bc1;
                v0 = v0 > 0.f ? v0 : 0.f; v1 = v1 > 0.f ? v1 : 0.f;
                v2 = v2 > 0.f ? v2 : 0.f; v3 = v3 > 0.f ? v3 : 0.f;
                int r = r0 + mt * 16;
                uint32_t lo;
                uint32_t hi = pack_bf16_hi(v0, v1, lo);
                uint32_t off = (uint32_t)r * PADB + (uint32_t)c * 2;
                *reinterpret_cast<uint32_t*>(sm + SM_AHI + off) = hi;
                *reinterpret_cast<uint32_t*>(sm + SM_ALO + off) = lo;
                hi = pack_bf16_hi(v2, v3, lo);
                off = (uint32_t)(r + 8) * PADB + (uint32_t)c * 2;
                *reinterpret_cast<uint32_t*>(sm + SM_AHI + off) = hi;
                *reinterpret_cast<uint32_t*>(sm + SM_ALO + off) = lo;
            }
        }
    }
    // ---- copy Wb blobs ----
    {
        const float4* sh = reinterpret_cast<const float4*>(WbHi);
        const float4* sl = reinterpret_cast<const float4*>(WbLo);
#pragma unroll
        for (int i = 0; i < 8; i++) {
            int idx = i * 256 + tid;
            int row = idx >> 4, c16 = idx & 15;
            uint32_t off = (uint32_t)row * PADB + (uint32_t)c16 * 16;
            *reinterpret_cast<float4*>(sm + SM_WHI + off) = sh[idx];
            *reinterpret_cast<float4*>(sm + SM_WLO + off) = sl[idx];
        }
    }
    __syncthreads();

    do_gemm(smb, wm, wn, lane, acc);

    // ---- epilogue 2 ----
    const int r0 = wm * 32 + (lane >> 2);
    if (Wfc == nullptr) {
#pragma unroll
        for (int mt = 0; mt < 2; mt++) {
            int ra = m_base + r0 + mt * 16;
            int rb = ra + 8;
#pragma unroll
            for (int nt = 0; nt < 8; nt++) {
                int c = wn * 64 + nt * 8 + (lane & 3) * 2;
                float bc0 = __ldg(bb + c), bc1 = __ldg(bb + c + 1);
                float v0 = acc[mt][nt][0] + bc0;
                float v1 = acc[mt][nt][1] + bc1;
                float v2 = acc[mt][nt][2] + bc0;
                float v3 = acc[mt][nt][3] + bc1;
                if (final_relu) {
                    v0 = v0 > 0.f ? v0 : 0.f; v1 = v1 > 0.f ? v1 : 0.f;
                    v2 = v2 > 0.f ? v2 : 0.f; v3 = v3 > 0.f ? v3 : 0.f;
                }
                if (ra < NND) *reinterpret_cast<float2*>(out + (size_t)ra * 128 + c) = make_float2(v0, v1);
                if (rb < NND) *reinterpret_cast<float2*>(out + (size_t)rb * 128 + c) = make_float2(v2, v3);
            }
        }
    } else {
        float* fcb = reinterpret_cast<float*>(sm + SM_FC);
#pragma unroll
        for (int mt = 0; mt < 2; mt++) {
            float sa0 = 0.f, sa1 = 0.f, sb0 = 0.f, sb1 = 0.f;
#pragma unroll
            for (int nt = 0; nt < 8; nt++) {
                int c = wn * 64 + nt * 8 + (lane & 3) * 2;
                float bc0 = __ldg(bb + c), bc1 = __ldg(bb + c + 1);
                float w00 = __ldg(Wfc + c * 2),       w01 = __ldg(Wfc + c * 2 + 1);
                float w10 = __ldg(Wfc + (c + 1) * 2), w11 = __ldg(Wfc + (c + 1) * 2 + 1);
                float v0 = acc[mt][nt][0] + bc0;
                float v1 = acc[mt][nt][1] + bc1;
                float v2 = acc[mt][nt][2] + bc0;
                float v3 = acc[mt][nt][3] + bc1;
                sa0 += v0 * w00 + v1 * w10;
                sa1 += v0 * w01 + v1 * w11;
                sb0 += v2 * w00 + v3 * w10;
                sb1 += v2 * w01 + v3 * w11;
            }
#pragma unroll
            for (int o = 1; o < 4; o <<= 1) {
                sa0 += __shfl_xor_sync(0xffffffffu, sa0, o);
                sa1 += __shfl_xor_sync(0xffffffffu, sa1, o);
                sb0 += __shfl_xor_sync(0xffffffffu, sb0, o);
                sb1 += __shfl_xor_sync(0xffffffffu, sb1, o);
            }
            if ((lane & 3) == 0) {
                int r = r0 + mt * 16;
                fcb[(r * 2 + wn) * 2 + 0] = sa0;
                fcb[(r * 2 + wn) * 2 + 1] = sa1;
                fcb[((r + 8) * 2 + wn) * 2 + 0] = sb0;
                fcb[((r + 8) * 2 + wn) * 2 + 1] = sb1;
            }
        }
        __syncthreads();
        if (tid < 128) {
            int m = m_base + tid;
            if (m < NND) {
                out[(size_t)m * 2 + 0] = fcb[tid * 4 + 0] + fcb[tid * 4 + 2] + __ldg(bfc + 0);
                out[(size_t)m * 2 + 1] = fcb[tid * 4 + 1] + fcb[tid * 4 + 3] + __ldg(bfc + 1);
            }
        }
    }
}

// ---------------- launch ----------------
extern "C" void kernel_launch(void* const* d_in, const int* in_sizes, int n_in,
                              void* d_out, int out_size) {
    const float* x   = (const float*)d_in[0];
    const void*  ei  = d_in[1];
    const float* W1a = (const float*)d_in[2];
    const float* b1a = (const float*)d_in[3];
    const float* W1b = (const float*)d_in[4];
    const float* b1b = (const float*)d_in[5];
    const float* W2a = (const float*)d_in[6];
    const float* b2a = (const float*)d_in[7];
    const float* W2b = (const float*)d_in[8];
    const float* b2b = (const float*)d_in[9];
    const float* Wfc = (const float*)d_in[10];
    const float* bfc = (const float*)d_in[11];
    float* out = (float*)d_out;

    void *pA = nullptr, *pB = nullptr, *pW = nullptr;
    cudaGetSymbolAddress(&pA, g_bufA);
    cudaGetSymbolAddress(&pB, g_bufB);
    cudaGetSymbolAddress(&pW, g_wb);
    const __nv_bfloat16* wb = (const __nv_bfloat16*)pW;

    cudaFuncSetAttribute(k_mlp_mma, cudaFuncAttributeMaxDynamicSharedMemorySize, SM_TOTAL);

    const int GMLP = (NND + 127) / 128;   // 391
    const int GW   = (NND + 7) / 8;       // static warp-per-node gather

    k_zero_deg<<<(NND + 255) / 256, 256>>>((const long long*)ei);
    k_hist<<<HISTB + 4, 256>>>(ei, W1a, W1b, W2a, W2b);
    k_s1<<<NSB, SCB>>>();
    k_s23<<<NSB, SCB>>>();
    k_fill<<<NE / 256, 256>>>(ei);

    // layer 1
    k_gather<<<GW, 256>>>((const float4*)x, (float4*)pA);
    k_mlp_mma<<<GMLP, 256, SM_TOTAL>>>((const float*)pA,
        wb + 0 * 16384, wb + 1 * 16384, wb + 2 * 16384, wb + 3 * 16384,
        b1a, b1b, (float*)pB, 1, nullptr, nullptr);
    // layer 2 + FC head
    k_gather<<<GW, 256>>>((const float4*)pB, (float4*)pA);
    k_mlp_mma<<<GMLP, 256, SM_TOTAL>>>((const float*)pA,
        wb + 4 * 16384, wb + 5 * 16384, wb + 6 * 16384, wb + 7 * 16384,
        b2a, b2b, out, 0, Wfc, bfc);
}

// round 16
// speedup vs baseline: 1.0651x; 1.0631x over previous
#include <cuda_runtime.h>
#include <cuda_bf16.h>
#include <cuda_fp16.h>
#include <cstdint>

#define NND 50000
#define NE  800000
#define HID 128

#define SCB 256
#define NSB ((NND + SCB - 1) / SCB)
#define ZB  ((NND + 255) / 256)
#define CVB ((NND + 127) / 128)   // 391 convert blocks

#define PADB 272           // bytes per smem tile row (128 bf16 + 8 pad)
#define TILEB (128 * PADB)

#define SM_AHI 0
#define SM_ALO (SM_AHI + TILEB)
#define SM_WHI (SM_ALO + TILEB)
#define SM_WLO (SM_WHI + TILEB)
#define SM_FC  (SM_WLO + TILEB)
#define SM_TOTAL (SM_FC + 128 * 4 * 4)

// ---------------- device scratch ----------------
__device__ int   g_deg[NND];
__device__ int   g_rowptr[NND + 1];
__device__ int   g_cursor[NND];
__device__ int   g_col[NE];
__device__ int   g_part[NSB];
__device__ float g_bufA[(size_t)NND * HID];     // fp32 agg (MLP input)
__device__ uint2 g_bufH[(size_t)NND * 32];      // fp16 feature rows (gather input)
__device__ __nv_bfloat16 g_wb[8][16384];        // {W1a,W1b,W2a,W2b} x {hi,lo}
__device__ int   g_is64;

// ---------------- PTX helpers ----------------
__device__ __forceinline__ uint32_t smem_u32(const void* p) {
    uint32_t a;
    asm("{ .reg .u64 t; cvta.to.shared.u64 t, %1; cvt.u32.u64 %0, t; }" : "=r"(a) : "l"(p));
    return a;
}
__device__ __forceinline__ void ldsm_x4(uint32_t* r, uint32_t addr) {
    asm volatile("ldmatrix.sync.aligned.m8n8.x4.shared.b16 {%0,%1,%2,%3}, [%4];"
                 : "=r"(r[0]), "=r"(r[1]), "=r"(r[2]), "=r"(r[3]) : "r"(addr));
}
__device__ __forceinline__ void ldsm_x2(uint32_t* r, uint32_t addr) {
    asm volatile("ldmatrix.sync.aligned.m8n8.x2.shared.b16 {%0,%1}, [%2];"
                 : "=r"(r[0]), "=r"(r[1]) : "r"(addr));
}
__device__ __forceinline__ void mma16816(float* c, const uint32_t* a, const uint32_t* b) {
    asm volatile("mma.sync.aligned.m16n8k16.row.col.f32.bf16.bf16.f32 "
                 "{%0,%1,%2,%3}, {%4,%5,%6,%7}, {%8,%9}, {%0,%1,%2,%3};"
                 : "+f"(c[0]), "+f"(c[1]), "+f"(c[2]), "+f"(c[3])
                 : "r"(a[0]), "r"(a[1]), "r"(a[2]), "r"(a[3]), "r"(b[0]), "r"(b[1]));
}
__device__ __forceinline__ uint32_t pack_bf16_hi(float v0, float v1, uint32_t& lop) {
    __nv_bfloat16 h0 = __float2bfloat16(v0);
    __nv_bfloat16 h1 = __float2bfloat16(v1);
    __nv_bfloat16 l0 = __float2bfloat16(v0 - __bfloat162float(h0));
    __nv_bfloat16 l1 = __float2bfloat16(v1 - __bfloat162float(h1));
    lop = ((uint32_t)__bfloat16_as_ushort(l1) << 16) | __bfloat16_as_ushort(l0);
    return ((uint32_t)__bfloat16_as_ushort(h1) << 16) | __bfloat16_as_ushort(h0);
}
__device__ __forceinline__ void acc_u2(float4& a, uint2 u) {
    float2 lo = __half22float2(*reinterpret_cast<__half2*>(&u.x));
    float2 hi = __half22float2(*reinterpret_cast<__half2*>(&u.y));
    a.x += lo.x; a.y += lo.y; a.z += hi.x; a.w += hi.y;
}

// ---------------- zero deg + detect + convert x -> fp16 (merged) ----------------
__global__ void k_zero_cvt(const long long* __restrict__ ei,
                           const float4* __restrict__ x4) {
    if (blockIdx.x >= ZB) {
        int base_row = (blockIdx.x - ZB) * 128;
        for (int idx = threadIdx.x; idx < 128 * 32; idx += 256) {
            int row = base_row + (idx >> 5);
            if (row < NND) {
                float4 v = x4[(size_t)row * 32 + (idx & 31)];
                uint2 u;
                *reinterpret_cast<__half2*>(&u.x) = __floats2half2_rn(v.x, v.y);
                *reinterpret_cast<__half2*>(&u.y) = __floats2half2_rn(v.z, v.w);
                g_bufH[(size_t)row * 32 + (idx & 31)] = u;
            }
        }
        return;
    }
    int i = blockIdx.x * blockDim.x + threadIdx.x;
    if (i < NND) g_deg[i] = 0;
    if (blockIdx.x == 0 && threadIdx.x < 32) {
        int lane = threadIdx.x;
        unsigned long long h = ((unsigned long long)ei[lane]) >> 32;
        h |= ((unsigned long long)ei[lane + 32]) >> 32;
        unsigned any = __ballot_sync(0xffffffffu, h != 0ull);
        if (lane == 0) g_is64 = (any == 0u) ? 1 : 0;
    }
}

// ---------------- histogram + weight prep (merged) ----------------
#define HISTB (NE / 256)   // 3125
__global__ void k_hist(const void* __restrict__ ei,
                       const float* __restrict__ W0, const float* __restrict__ W1,
                       const float* __restrict__ W2, const float* __restrict__ W3) {
    if (blockIdx.x >= HISTB) {
        int mat = blockIdx.x - HISTB;
        const float* W = (mat == 0) ? W0 : (mat == 1) ? W1 : (mat == 2) ? W2 : W3;
        uint32_t* hiB = reinterpret_cast<uint32_t*>(g_wb[mat * 2]);
        uint32_t* loB = reinterpret_cast<uint32_t*>(g_wb[mat * 2 + 1]);
        for (int idx = threadIdx.x; idx < 8192; idx += blockDim.x) {
            int kp = idx & 63, n = idx >> 6, k = kp * 2;
            float a0 = W[k * 128 + n];
            float a1 = W[(k + 1) * 128 + n];
            uint32_t lp, hp = pack_bf16_hi(a0, a1, lp);
            hiB[n * 64 + kp] = hp;
            loB[n * 64 + kp] = lp;
        }
        return;
    }
    int e = blockIdx.x * blockDim.x + threadIdx.x;
    int d;
    if (g_is64) d = (int)reinterpret_cast<const long long*>(ei)[NE + e];
    else        d = reinterpret_cast<const int*>(ei)[NE + e];
    atomicAdd(&g_deg[d], 1);
}

// ---------------- scan phase 1: per-block sums ----------------
__global__ void k_s1() {
    int b = blockIdx.x, t = threadIdx.x;
    int idx = b * SCB + t;
    int v = (idx < NND) ? g_deg[idx] : 0;
#pragma unroll
    for (int o = 16; o; o >>= 1) v += __shfl_down_sync(0xffffffffu, v, o);
    __shared__ int ws[8];
    if ((t & 31) == 0) ws[t >> 5] = v;
    __syncthreads();
    if (t == 0) {
        int s = 0;
#pragma unroll
        for (int i = 0; i < 8; i++) s += ws[i];
        g_part[b] = s;
    }
}

// ---------------- scan phase 2+3 fused ----------------
__global__ void k_s23() {
    int b = blockIdx.x, t = threadIdx.x, lane = t & 31, w = t >> 5;
    __shared__ int ws[8], wso[8];
    __shared__ int sbase;
    int pv = (t < b) ? g_part[t] : 0;
#pragma unroll
    for (int o = 16; o; o >>= 1) pv += __shfl_down_sync(0xffffffffu, pv, o);
    if (lane == 0) ws[w] = pv;
    __syncthreads();
    if (t == 0) {
        int s = 0;
#pragma unroll
        for (int i = 0; i < 8; i++) s += ws[i];
        sbase = s;
        if (b == 0) g_rowptr[NND] = NE;
    }
    __syncthreads();
    const int base = sbase;
    int idx = b * SCB + t;
    int v = (idx < NND) ? g_deg[idx] : 0;
    int iv = v;
#pragma unroll
    for (int o = 1; o < 32; o <<= 1) {
        int u = __shfl_up_sync(0xffffffffu, iv, o);
        if (lane >= o) iv += u;
    }
    __syncthreads();
    if (lane == 31) ws[w] = iv;
    __syncthreads();
    if (t == 0) {
        int run = 0;
#pragma unroll
        for (int i = 0; i < 8; i++) { wso[i] = run; run += ws[i]; }
    }
    __syncthreads();
    int excl = base + wso[w] + iv - v;
    if (idx < NND) { g_rowptr[idx] = excl; g_cursor[idx] = excl; }
}

__global__ void k_fill(const void* __restrict__ ei) {
    int e = blockIdx.x * blockDim.x + threadIdx.x;
    if (e >= NE) return;
    int s, d;
    if (g_is64) {
        s = (int)reinterpret_cast<const long long*>(ei)[e];
        d = (int)reinterpret_cast<const long long*>(ei)[NE + e];
    } else {
        s = reinterpret_cast<const int*>(ei)[e];
        d = reinterpret_cast<const int*>(ei)[NE + e];
    }
    int pos = atomicAdd(&g_cursor[d], 1);
    g_col[pos] = s;
}

// ---------------- fp16 gather: agg[i] = h[i] + sum_{j in N(i)} h[j]  (fp32 out) ----------------
__global__ void k_gather16(float4* __restrict__ out4) {
    int node = (int)((blockIdx.x * blockDim.x + threadIdx.x) >> 5);
    if (node >= NND) return;
    int lane = threadIdx.x & 31;
    const uint2* in2 = g_bufH;
    float4 a0 = make_float4(0.f, 0.f, 0.f, 0.f);
    float4 a1 = a0, a2 = a0, a3 = a0;
    acc_u2(a0, in2[(size_t)node * 32 + lane]);
    int beg = g_rowptr[node], end = g_rowptr[node + 1];
    int k = beg;
    for (; k + 8 <= end; k += 8) {
        int j0 = g_col[k],     j1 = g_col[k + 1], j2 = g_col[k + 2], j3 = g_col[k + 3];
        int j4 = g_col[k + 4], j5 = g_col[k + 5], j6 = g_col[k + 6], j7 = g_col[k + 7];
        uint2 u0 = in2[(size_t)j0 * 32 + lane];
        uint2 u1 = in2[(size_t)j1 * 32 + lane];
        uint2 u2 = in2[(size_t)j2 * 32 + lane];
        uint2 u3 = in2[(size_t)j3 * 32 + lane];
        uint2 u4 = in2[(size_t)j4 * 32 + lane];
        uint2 u5 = in2[(size_t)j5 * 32 + lane];
        uint2 u6 = in2[(size_t)j6 * 32 + lane];
        uint2 u7 = in2[(size_t)j7 * 32 + lane];
        acc_u2(a0, u0); acc_u2(a1, u1); acc_u2(a2, u2); acc_u2(a3, u3);
        acc_u2(a0, u4); acc_u2(a1, u5); acc_u2(a2, u6); acc_u2(a3, u7);
    }
    for (; k + 4 <= end; k += 4) {
        int j0 = g_col[k], j1 = g_col[k + 1], j2 = g_col[k + 2], j3 = g_col[k + 3];
        uint2 u0 = in2[(size_t)j0 * 32 + lane];
        uint2 u1 = in2[(size_t)j1 * 32 + lane];
        uint2 u2 = in2[(size_t)j2 * 32 + lane];
        uint2 u3 = in2[(size_t)j3 * 32 + lane];
        acc_u2(a0, u0); acc_u2(a1, u1); acc_u2(a2, u2); acc_u2(a3, u3);
    }
    for (; k < end; k++) {
        acc_u2(a0, in2[(size_t)g_col[k] * 32 + lane]);
    }
    a0.x += a1.x + a2.x + a3.x;
    a0.y += a1.y + a2.y + a3.y;
    a0.z += a1.z + a2.z + a3.z;
    a0.w += a1.w + a2.w + a3.w;
    out4[(size_t)node * 32 + lane] = a0;
}

// ---------------- GEMM core: 3-phase bf16 split, acc in fp32 (8-warp layout) ----------------
__device__ __forceinline__ void do_gemm(uint32_t smb, int wm, int wn, int lane,
                                        float acc[2][8][4]) {
#pragma unroll
    for (int mt = 0; mt < 2; mt++)
#pragma unroll
        for (int nt = 0; nt < 8; nt++)
#pragma unroll
            for (int i = 0; i < 4; i++) acc[mt][nt][i] = 0.f;

    const uint32_t a_bases[3] = { smb + SM_AHI, smb + SM_AHI, smb + SM_ALO };
    const uint32_t w_bases[3] = { smb + SM_WHI, smb + SM_WLO, smb + SM_WHI };

    const int a_row0 = wm * 32 + (lane & 15);
    const int a_cofs = (lane >> 4) * 8;
    const int b_row0 = wn * 64 + (lane & 7);
    const int b_cofs = ((lane >> 3) & 1) * 8;

#pragma unroll
    for (int p = 0; p < 3; p++) {
        const uint32_t Ab = a_bases[p];
        const uint32_t Wb = w_bases[p];
#pragma unroll
        for (int ks = 0; ks < 8; ks++) {
            const int k0 = ks * 16;
            uint32_t afrag[2][4];
#pragma unroll
            for (int mt = 0; mt < 2; mt++)
                ldsm_x4(afrag[mt], Ab + (uint32_t)(a_row0 + mt * 16) * PADB
                                      + (uint32_t)(k0 + a_cofs) * 2);
            uint32_t bfrag[8][2];
#pragma unroll
            for (int nt = 0; nt < 8; nt++)
                ldsm_x2(bfrag[nt], Wb + (uint32_t)(b_row0 + nt * 8) * PADB
                                      + (uint32_t)(k0 + b_cofs) * 2);
#pragma unroll
            for (int mt = 0; mt < 2; mt++)
#pragma unroll
                for (int nt = 0; nt < 8; nt++)
                    mma16816(acc[mt][nt], afrag[mt], bfrag[nt]);
        }
    }
}

// ---------------- MLP kernel (256 threads, proven shape) ----------------
// hidden mode (Wfc==nullptr): writes fp16 rows into g_bufH
// fc mode: writes [NND,2] fp32 into out
__global__ void __launch_bounds__(256, 1) k_mlp_mma(
    const float* __restrict__ A,
    const __nv_bfloat16* __restrict__ WaHi, const __nv_bfloat16* __restrict__ WaLo,
    const __nv_bfloat16* __restrict__ WbHi, const __nv_bfloat16* __restrict__ WbLo,
    const float* __restrict__ ba, const float* __restrict__ bb,
    float* __restrict__ out, int final_relu,
    const float* __restrict__ Wfc, const float* __restrict__ bfc) {
    extern __shared__ char sm[];
    const uint32_t smb = smem_u32(sm);
    const int tid = threadIdx.x;
    const int wid = tid >> 5;
    const int lane = tid & 31;
    const int wm = wid & 3;
    const int wn = wid >> 2;
    const int m_base = blockIdx.x * 128;

    // ---- load A tile: fp32 -> bf16 hi/lo ----
    {
#pragma unroll
        for (int it = 0; it < 16; it++) {
            int r = wid * 16 + it;
            int m = m_base + r;
            float4 v = make_float4(0.f, 0.f, 0.f, 0.f);
            if (m < NND) v = *reinterpret_cast<const float4*>(A + (size_t)m * 128 + lane * 4);
            uint32_t l0, l1;
            uint32_t h0 = pack_bf16_hi(v.x, v.y, l0);
            uint32_t h1 = pack_bf16_hi(v.z, v.w, l1);
            uint32_t off = (uint32_t)r * PADB + (uint32_t)lane * 8;
            *reinterpret_cast<uint2*>(sm + SM_AHI + off) = make_uint2(h0, h1);
            *reinterpret_cast<uint2*>(sm + SM_ALO + off) = make_uint2(l0, l1);
        }
    }
    // ---- copy Wa blobs ----
    {
        const float4* sh = reinterpret_cast<const float4*>(WaHi);
        const float4* sl = reinterpret_cast<const float4*>(WaLo);
#pragma unroll
        for (int i = 0; i < 8; i++) {
            int idx = i * 256 + tid;
            int row = idx >> 4, c16 = idx & 15;
            uint32_t off = (uint32_t)row * PADB + (uint32_t)c16 * 16;
            *reinterpret_cast<float4*>(sm + SM_WHI + off) = sh[idx];
            *reinterpret_cast<float4*>(sm + SM_WLO + off) = sl[idx];
        }
    }
    __syncthreads();

    float acc[2][8][4];
    do_gemm(smb, wm, wn, lane, acc);
    __syncthreads();

    // ---- epilogue 1: bias + relu -> back into A tile ----
    {
        const int r0 = wm * 32 + (lane >> 2);
#pragma unroll
        for (int mt = 0; mt < 2; mt++) {
#pragma unroll
            for (int nt = 0; nt < 8; nt++) {
                int c = wn * 64 + nt * 8 + (lane & 3) * 2;
                float bc0 = __ldg(ba + c), bc1 = __ldg(ba + c + 1);
                float v0 = acc[mt][nt][0] + bc0;
                float v1 = acc[mt][nt][1] + bc1;
                float v2 = acc[mt][nt][2] + bc0;
                float v3 = acc[mt][nt][3] + bc1;
                v0 = v0 > 0.f ? v0 : 0.f; v1 = v1 > 0.f ? v1 : 0.f;
                v2 = v2 > 0.f ? v2 : 0.f; v3 = v3 > 0.f ? v3 : 0.f;
                int r = r0 + mt * 16;
                uint32_t lo;
                uint32_t hi = pack_bf16_hi(v0, v1, lo);
                uint32_t off = (uint32_t)r * PADB + (uint32_t)c * 2;
                *reinterpret_cast<uint32_t*>(sm + SM_AHI + off) = hi;
                *reinterpret_cast<uint32_t*>(sm + SM_ALO + off) = lo;
                hi = pack_bf16_hi(v2, v3, lo);
                off = (uint32_t)(r + 8) * PADB + (uint32_t)c * 2;
                *reinterpret_cast<uint32_t*>(sm + SM_AHI + off) = hi;
                *reinterpret_cast<uint32_t*>(sm + SM_ALO + off) = lo;
            }
        }
    }
    // ---- copy Wb blobs ----
    {
        const float4* sh = reinterpret_cast<const float4*>(WbHi);
        const float4* sl = reinterpret_cast<const float4*>(WbLo);
#pragma unroll
        for (int i = 0; i < 8; i++) {
            int idx = i * 256 + tid;
            int row = idx >> 4, c16 = idx & 15;
            uint32_t off = (uint32_t)row * PADB + (uint32_t)c16 * 16;
            *reinterpret_cast<float4*>(sm + SM_WHI + off) = sh[idx];
            *reinterpret_cast<float4*>(sm + SM_WLO + off) = sl[idx];
        }
    }
    __syncthreads();

    do_gemm(smb, wm, wn, lane, acc);

    // ---- epilogue 2 ----
    const int r0 = wm * 32 + (lane >> 2);
    if (Wfc == nullptr) {
        // hidden mode: write fp16 rows to g_bufH
        __half2* oh = reinterpret_cast<__half2*>(g_bufH);
#pragma unroll
        for (int mt = 0; mt < 2; mt++) {
            int ra = m_base + r0 + mt * 16;
            int rb = ra + 8;
#pragma unroll
            for (int nt = 0; nt < 8; nt++) {
                int c = wn * 64 + nt * 8 + (lane & 3) * 2;
                float bc0 = __ldg(bb + c), bc1 = __ldg(bb + c + 1);
                float v0 = acc[mt][nt][0] + bc0;
                float v1 = acc[mt][nt][1] + bc1;
                float v2 = acc[mt][nt][2] + bc0;
                float v3 = acc[mt][nt][3] + bc1;
                if (final_relu) {
                    v0 = v0 > 0.f ? v0 : 0.f; v1 = v1 > 0.f ? v1 : 0.f;
                    v2 = v2 > 0.f ? v2 : 0.f; v3 = v3 > 0.f ? v3 : 0.f;
                }
                if (ra < NND) oh[(size_t)ra * 64 + (c >> 1)] = __floats2half2_rn(v0, v1);
                if (rb < NND) oh[(size_t)rb * 64 + (c >> 1)] = __floats2half2_rn(v2, v3);
            }
        }
    } else {
        float* fcb = reinterpret_cast<float*>(sm + SM_FC);
#pragma unroll
        for (int mt = 0; mt < 2; mt++) {
            float sa0 = 0.f, sa1 = 0.f, sb0 = 0.f, sb1 = 0.f;
#pragma unroll
            for (int nt = 0; nt < 8; nt++) {
                int c = wn * 64 + nt * 8 + (lane & 3) * 2;
                float bc0 = __ldg(bb + c), bc1 = __ldg(bb + c + 1);
                float w00 = __ldg(Wfc + c * 2),       w01 = __ldg(Wfc + c * 2 + 1);
                float w10 = __ldg(Wfc + (c + 1) * 2), w11 = __ldg(Wfc + (c + 1) * 2 + 1);
                float v0 = acc[mt][nt][0] + bc0;
                float v1 = acc[mt][nt][1] + bc1;
                float v2 = acc[mt][nt][2] + bc0;
                float v3 = acc[mt][nt][3] + bc1;
                sa0 += v0 * w00 + v1 * w10;
                sa1 += v0 * w01 + v1 * w11;
                sb0 += v2 * w00 + v3 * w10;
                sb1 += v2 * w01 + v3 * w11;
            }
#pragma unroll
            for (int o = 1; o < 4; o <<= 1) {
                sa0 += __shfl_xor_sync(0xffffffffu, sa0, o);
                sa1 += __shfl_xor_sync(0xffffffffu, sa1, o);
                sb0 += __shfl_xor_sync(0xffffffffu, sb0, o);
                sb1 += __shfl_xor_sync(0xffffffffu, sb1, o);
            }
            if ((lane & 3) == 0) {
                int r = r0 + mt * 16;
                fcb[(r * 2 + wn) * 2 + 0] = sa0;
                fcb[(r * 2 + wn) * 2 + 1] = sa1;
                fcb[((r + 8) * 2 + wn) * 2 + 0] = sb0;
                fcb[((r + 8) * 2 + wn) * 2 + 1] = sb1;
            }
        }
        __syncthreads();
        if (tid < 128) {
            int m = m_base + tid;
            if (m < NND) {
                out[(size_t)m * 2 + 0] = fcb[tid * 4 + 0] + fcb[tid * 4 + 2] + __ldg(bfc + 0);
                out[(size_t)m * 2 + 1] = fcb[tid * 4 + 1] + fcb[tid * 4 + 3] + __ldg(bfc + 1);
            }
        }
    }
}

// ---------------- launch ----------------
extern "C" void kernel_launch(void* const* d_in, const int* in_sizes, int n_in,
                              void* d_out, int out_size) {
    const float* x   = (const float*)d_in[0];
    const void*  ei  = d_in[1];
    const float* W1a = (const float*)d_in[2];
    const float* b1a = (const float*)d_in[3];
    const float* W1b = (const float*)d_in[4];
    const float* b1b = (const float*)d_in[5];
    const float* W2a = (const float*)d_in[6];
    const float* b2a = (const float*)d_in[7];
    const float* W2b = (const float*)d_in[8];
    const float* b2b = (const float*)d_in[9];
    const float* Wfc = (const float*)d_in[10];
    const float* bfc = (const float*)d_in[11];
    float* out = (float*)d_out;

    void *pA = nullptr, *pW = nullptr;
    cudaGetSymbolAddress(&pA, g_bufA);
    cudaGetSymbolAddress(&pW, g_wb);
    const __nv_bfloat16* wb = (const __nv_bfloat16*)pW;

    cudaFuncSetAttribute(k_mlp_mma, cudaFuncAttributeMaxDynamicSharedMemorySize, SM_TOTAL);

    const int GMLP = (NND + 127) / 128;   // 391
    const int GW   = (NND + 7) / 8;       // static warp-per-node gather

    k_zero_cvt<<<ZB + CVB, 256>>>((const long long*)ei, (const float4*)x);
    k_hist<<<HISTB + 4, 256>>>(ei, W1a, W1b, W2a, W2b);
    k_s1<<<NSB, SCB>>>();
    k_s23<<<NSB, SCB>>>();
    k_fill<<<NE / 256, 256>>>(ei);

    // layer 1: gather(x16) -> fp32 agg -> MLP1 -> h1 (fp16, into g_bufH)
    k_gather16<<<GW, 256>>>((float4*)pA);
    k_mlp_mma<<<GMLP, 256, SM_TOTAL>>>((const float*)pA,
        wb + 0 * 16384, wb + 1 * 16384, wb + 2 * 16384, wb + 3 * 16384,
        b1a, b1b, nullptr, 1, nullptr, nullptr);
    // layer 2: gather(h1_16) -> fp32 agg -> MLP2 + FC head -> out
    k_gather16<<<GW, 256>>>((float4*)pA);
    k_mlp_mma<<<GMLP, 256, SM_TOTAL>>>((const float*)pA,
        wb + 4 * 16384, wb + 5 * 16384, wb + 6 * 16384, wb + 7 * 16384,
        b2a, b2b, out, 0, Wfc, bfc);
}